// round 3
// baseline (speedup 1.0000x reference)
#include <cuda_runtime.h>
#include <math.h>

#define BQ 2
#define CQ 80
#define HQ 32
#define WQ 88
#define PIX (HQ * WQ)          // 2816 pixels
#define NPTS 262144            // 128*128*16 points per batch
#define PTS_PER_BLK 64
#define THREADS 256
#define CG 20                  // 80 channels = 20 float4 groups
#define ITEMS (PTS_PER_BLK * CG)   // 1280 work items per block
#define SROW 21                // s_out row stride in float4 units

// Transposed features: (B, H*W, C) so channels are contiguous per pixel.
__device__ float g_featT[BQ * PIX * CQ];
// Combined 3x4 projection matrix per batch: F = (intr*scale) * extr * bda
__device__ float g_F[BQ][12];

// ---------------- prep: tiled transpose (B,C,HW) -> (B,HW,C) + matrices ----------------
__global__ void prep_kernel(const float* __restrict__ feat,
                            const float* __restrict__ intrin,
                            const float* __restrict__ extrin,
                            const float* __restrict__ bda) {
    __shared__ float tile[32][33];
    // matrices: done by the first 2 threads of block (0,0,0)
    if (blockIdx.x == 0 && blockIdx.y == 0 && blockIdx.z == 0 &&
        threadIdx.y == 0 && threadIdx.x < BQ) {
        int b = threadIdx.x;
        const float* In = intrin + b * 16;
        const float* Ex = extrin + b * 16;
        const float* Bd = bda + b * 16;
        float P[3][4];
        for (int r = 0; r < 3; r++) {
            float s = (r < 2) ? 0.125f : 1.0f;
            for (int cc = 0; cc < 4; cc++) {
                float acc = 0.0f;
                for (int k = 0; k < 3; k++)
                    acc += In[r * 4 + k] * s * Ex[k * 4 + cc];
                P[r][cc] = acc;
            }
        }
        for (int r = 0; r < 3; r++)
            for (int cc = 0; cc < 4; cc++) {
                float acc = 0.0f;
                for (int k = 0; k < 4; k++)
                    acc += P[r][k] * Bd[k * 4 + cc];
                g_F[b][r * 4 + cc] = acc;
            }
    }
    int b = blockIdx.z;
    int ct = blockIdx.y * 32;   // channel tile base
    int pt = blockIdx.x * 32;   // pixel tile base
    int tx = threadIdx.x, ty = threadIdx.y;   // (32,8)
    const float* src = feat + (size_t)b * CQ * PIX;
    #pragma unroll
    for (int j = 0; j < 32; j += 8) {
        int c = ct + ty + j;
        int p = pt + tx;
        if (c < CQ && p < PIX)
            tile[ty + j][tx] = src[(size_t)c * PIX + p];
    }
    __syncthreads();
    float* dst = g_featT + (size_t)b * PIX * CQ;
    #pragma unroll
    for (int j = 0; j < 32; j += 8) {
        int p = pt + ty + j;
        int c = ct + tx;
        if (c < CQ && p < PIX)
            dst[(size_t)p * CQ + c] = tile[tx][ty + j];
    }
}

// ---------------- main kernel ----------------
__global__ void __launch_bounds__(THREADS)
bev_kernel(float* __restrict__ out) {
    __shared__ float4 s_w4[PTS_PER_BLK];
    __shared__ int4   s_idx4[PTS_PER_BLK];        // pixel * CG (float4 group base)
    __shared__ float4 s_out4[PTS_PER_BLK * SROW]; // 64 rows x 21 float4

    const int bidx = blockIdx.x;
    const int b = bidx >> 12;                 // 4096 blocks per batch
    const int nbase = (bidx & 4095) * PTS_PER_BLK;
    const int tid = threadIdx.x;

    // ---- Phase A: geometry for 64 points ----
    if (tid < PTS_PER_BLK) {
        int n = nbase + tid;
        int ix = n >> 11;            // NY*NZ = 2048
        int iy = (n >> 4) & 127;     // NZ = 16
        int iz = n & 15;
        float X = -51.2f + ix * 0.8f;
        float Y = -51.2f + iy * 0.8f;
        float Z = -5.0f + iz * 0.5f;
        const float* F = g_F[b];
        float px = F[0] * X + F[1] * Y + F[2]  * Z + F[3];
        float py = F[4] * X + F[5] * Y + F[6]  * Z + F[7];
        float pz = F[8] * X + F[9] * Y + F[10] * Z + F[11];
        float u = px / pz;
        float v = py / pz;
        u = u / (float)WQ * 2.0f - 1.0f;
        v = v / (float)HQ * 2.0f - 1.0f;
        float x = (u + 1.0f) * 0.5f * (float)(WQ - 1);
        float y = (v + 1.0f) * 0.5f * (float)(HQ - 1);
        if (!(isfinite(x) && isfinite(y))) { x = -10.0f; y = -10.0f; }
        float x0f = floorf(x), y0f = floorf(y);
        float wx1 = x - x0f, wy1 = y - y0f;
        float wx0 = 1.0f - wx1, wy0 = 1.0f - wy1;
        float x1f = x0f + 1.0f, y1f = y0f + 1.0f;
        bool vx0 = (x0f >= 0.0f) && (x0f <= (float)(WQ - 1));
        bool vx1 = (x1f >= 0.0f) && (x1f <= (float)(WQ - 1));
        bool vy0 = (y0f >= 0.0f) && (y0f <= (float)(HQ - 1));
        bool vy1 = (y1f >= 0.0f) && (y1f <= (float)(HQ - 1));
        int xi0 = (int)fminf(fmaxf(x0f, 0.0f), (float)(WQ - 1));
        int xi1 = (int)fminf(fmaxf(x1f, 0.0f), (float)(WQ - 1));
        int yi0 = (int)fminf(fmaxf(y0f, 0.0f), (float)(HQ - 1));
        int yi1 = (int)fminf(fmaxf(y1f, 0.0f), (float)(HQ - 1));
        int4 id;
        id.x = (yi0 * WQ + xi0) * CG;
        id.y = (yi0 * WQ + xi1) * CG;
        id.z = (yi1 * WQ + xi0) * CG;
        id.w = (yi1 * WQ + xi1) * CG;
        s_idx4[tid] = id;
        float4 w;
        w.x = (vx0 && vy0) ? wx0 * wy0 : 0.0f;
        w.y = (vx1 && vy0) ? wx1 * wy0 : 0.0f;
        w.z = (vx0 && vy1) ? wx0 * wy1 : 0.0f;
        w.w = (vx1 && vy1) ? wx1 * wy1 : 0.0f;
        s_w4[tid] = w;
    }
    __syncthreads();

    // ---- Phase B: predicated gathers + bilinear combine (float4 channels) ----
    const float4* fT = (const float4*)(g_featT + (size_t)b * PIX * CQ);
    #pragma unroll
    for (int it = 0; it < ITEMS / THREADS; it++) {
        int i = it * THREADS + tid;   // 0..1279
        int p = i / CG;
        int g = i - p * CG;
        float4 w = s_w4[p];
        int4 id = s_idx4[p];
        float4 a = make_float4(0.f, 0.f, 0.f, 0.f);
        if (w.x != 0.0f) {
            float4 v = __ldg(&fT[id.x + g]);
            a.x += w.x * v.x; a.y += w.x * v.y; a.z += w.x * v.z; a.w += w.x * v.w;
        }
        if (w.y != 0.0f) {
            float4 v = __ldg(&fT[id.y + g]);
            a.x += w.y * v.x; a.y += w.y * v.y; a.z += w.y * v.z; a.w += w.y * v.w;
        }
        if (w.z != 0.0f) {
            float4 v = __ldg(&fT[id.z + g]);
            a.x += w.z * v.x; a.y += w.z * v.y; a.z += w.z * v.z; a.w += w.z * v.w;
        }
        if (w.w != 0.0f) {
            float4 v = __ldg(&fT[id.w + g]);
            a.x += w.w * v.x; a.y += w.w * v.y; a.z += w.w * v.z; a.w += w.w * v.w;
        }
        s_out4[p * SROW + g] = a;
    }
    __syncthreads();

    // ---- Phase C: LDS.128 rows + 4-lane rotation-shuffle transpose + coalesced STG.128 ----
    // quad task t: p4 = t & 15 (point quad), g = t >> 4 (channel group)
    // lane j of quad reads (4 channels of point 4*p4+j), ends with (channel 4g+j, 4 points)
    {
        float4* out4 = (float4*)out;
        const int w = tid & 31;
        const int wi = tid >> 5;
        const int j = w & 3;
        const int k = w >> 2;
        #pragma unroll
        for (int it = 0; it < 5; it++) {
            int t0 = it * 64 + wi * 8 + k;   // 0..319
            int p4 = t0 & 15;
            int g = t0 >> 4;
            float4 x = s_out4[(4 * p4 + j) * SROW + g];
            float d0 = 0.f, d1 = 0.f, d2 = 0.f, d3 = 0.f;
            #pragma unroll
            for (int t = 0; t < 4; t++) {
                int sel = (j - t) & 3;
                float v = (sel == 0) ? x.x : (sel == 1) ? x.y : (sel == 2) ? x.z : x.w;
                int srcLane = (w & ~3) | ((j + t) & 3);
                float r = __shfl_sync(0xffffffffu, v, srcLane);
                int q = (j + t) & 3;
                if (q == 0) d0 = r;
                else if (q == 1) d1 = r;
                else if (q == 2) d2 = r;
                else d3 = r;
            }
            int c = 4 * g + j;
            size_t idx = (size_t)(b * CQ + c) * (NPTS / 4) + (nbase >> 2) + p4;
            out4[idx] = make_float4(d0, d1, d2, d3);
        }
    }
}

extern "C" void kernel_launch(void* const* d_in, const int* in_sizes, int n_in,
                              void* d_out, int out_size) {
    const float* img_feats = (const float*)d_in[0];
    const float* intrin    = (const float*)d_in[1];
    const float* extrin    = (const float*)d_in[2];
    const float* bda       = (const float*)d_in[3];
    float* out = (float*)d_out;

    dim3 tgrid((PIX + 31) / 32, (CQ + 31) / 32, BQ);
    prep_kernel<<<tgrid, dim3(32, 8)>>>(img_feats, intrin, extrin, bda);

    int nblocks = BQ * (NPTS / PTS_PER_BLK);   // 8192
    bev_kernel<<<nblocks, THREADS>>>(out);
}

// round 4
// speedup vs baseline: 1.6193x; 1.6193x over previous
#include <cuda_runtime.h>
#include <math.h>

#define BQ 2
#define CQ 80
#define HQ 32
#define WQ 88
#define PIX (HQ * WQ)          // 2816 pixels
#define NPTS 262144            // 128*128*16 points per batch
#define PTS_PER_BLK 64
#define THREADS 256
#define CG 20                  // 80 channels = 20 float4 groups
#define ITEMS (PTS_PER_BLK * CG)   // 1280 work items per block
#define SROW4 24               // s_out row stride in float4 (96 floats = 0 mod 32 banks)

// Transposed features: (B, H*W, C) so channels are contiguous per pixel.
__device__ float g_featT[BQ * PIX * CQ];
// Combined 3x4 projection matrix per batch: F = (intr*scale) * extr * bda
__device__ float g_F[BQ][12];

// ---------------- prep: tiled transpose (B,C,HW) -> (B,HW,C) + matrices ----------------
__global__ void prep_kernel(const float* __restrict__ feat,
                            const float* __restrict__ intrin,
                            const float* __restrict__ extrin,
                            const float* __restrict__ bda) {
    __shared__ float tile[32][33];
    if (blockIdx.x == 0 && blockIdx.y == 0 && blockIdx.z == 0 &&
        threadIdx.y == 0 && threadIdx.x < BQ) {
        int b = threadIdx.x;
        const float* In = intrin + b * 16;
        const float* Ex = extrin + b * 16;
        const float* Bd = bda + b * 16;
        float P[3][4];
        for (int r = 0; r < 3; r++) {
            float s = (r < 2) ? 0.125f : 1.0f;
            for (int cc = 0; cc < 4; cc++) {
                float acc = 0.0f;
                for (int k = 0; k < 3; k++)
                    acc += In[r * 4 + k] * s * Ex[k * 4 + cc];
                P[r][cc] = acc;
            }
        }
        for (int r = 0; r < 3; r++)
            for (int cc = 0; cc < 4; cc++) {
                float acc = 0.0f;
                for (int k = 0; k < 4; k++)
                    acc += P[r][k] * Bd[k * 4 + cc];
                g_F[b][r * 4 + cc] = acc;
            }
    }
    int b = blockIdx.z;
    int ct = blockIdx.y * 32;
    int pt = blockIdx.x * 32;
    int tx = threadIdx.x, ty = threadIdx.y;   // (32,8)
    const float* src = feat + (size_t)b * CQ * PIX;
    #pragma unroll
    for (int j = 0; j < 32; j += 8) {
        int c = ct + ty + j;
        int p = pt + tx;
        if (c < CQ && p < PIX)
            tile[ty + j][tx] = src[(size_t)c * PIX + p];
    }
    __syncthreads();
    float* dst = g_featT + (size_t)b * PIX * CQ;
    #pragma unroll
    for (int j = 0; j < 32; j += 8) {
        int p = pt + ty + j;
        int c = ct + tx;
        if (c < CQ && p < PIX)
            dst[(size_t)p * CQ + c] = tile[tx][ty + j];
    }
}

// ---------------- main kernel ----------------
__global__ void __launch_bounds__(THREADS)
bev_kernel(float* __restrict__ out) {
    __shared__ float4 s_w4[PTS_PER_BLK];
    __shared__ int4   s_idx4[PTS_PER_BLK];          // pixel * CG (float4 group base)
    __shared__ float4 s_out4[PTS_PER_BLK * SROW4];  // 64 rows x 24 float4 (swizzled)

    const int bidx = blockIdx.x;
    const int b = bidx >> 12;                 // 4096 blocks per batch
    const int nbase = (bidx & 4095) * PTS_PER_BLK;
    const int tid = threadIdx.x;

    // ---- Phase A: geometry for 64 points ----
    if (tid < PTS_PER_BLK) {
        int n = nbase + tid;
        int ix = n >> 11;            // NY*NZ = 2048
        int iy = (n >> 4) & 127;     // NZ = 16
        int iz = n & 15;
        float X = -51.2f + ix * 0.8f;
        float Y = -51.2f + iy * 0.8f;
        float Z = -5.0f + iz * 0.5f;
        const float* F = g_F[b];
        float px = F[0] * X + F[1] * Y + F[2]  * Z + F[3];
        float py = F[4] * X + F[5] * Y + F[6]  * Z + F[7];
        float pz = F[8] * X + F[9] * Y + F[10] * Z + F[11];
        float u = px / pz;
        float v = py / pz;
        u = u / (float)WQ * 2.0f - 1.0f;
        v = v / (float)HQ * 2.0f - 1.0f;
        float x = (u + 1.0f) * 0.5f * (float)(WQ - 1);
        float y = (v + 1.0f) * 0.5f * (float)(HQ - 1);
        if (!(isfinite(x) && isfinite(y))) { x = -10.0f; y = -10.0f; }
        float x0f = floorf(x), y0f = floorf(y);
        float wx1 = x - x0f, wy1 = y - y0f;
        float wx0 = 1.0f - wx1, wy0 = 1.0f - wy1;
        float x1f = x0f + 1.0f, y1f = y0f + 1.0f;
        bool vx0 = (x0f >= 0.0f) && (x0f <= (float)(WQ - 1));
        bool vx1 = (x1f >= 0.0f) && (x1f <= (float)(WQ - 1));
        bool vy0 = (y0f >= 0.0f) && (y0f <= (float)(HQ - 1));
        bool vy1 = (y1f >= 0.0f) && (y1f <= (float)(HQ - 1));
        int xi0 = (int)fminf(fmaxf(x0f, 0.0f), (float)(WQ - 1));
        int xi1 = (int)fminf(fmaxf(x1f, 0.0f), (float)(WQ - 1));
        int yi0 = (int)fminf(fmaxf(y0f, 0.0f), (float)(HQ - 1));
        int yi1 = (int)fminf(fmaxf(y1f, 0.0f), (float)(HQ - 1));
        int4 id;
        id.x = (yi0 * WQ + xi0) * CG;
        id.y = (yi0 * WQ + xi1) * CG;
        id.z = (yi1 * WQ + xi0) * CG;
        id.w = (yi1 * WQ + xi1) * CG;
        s_idx4[tid] = id;
        float4 w;
        w.x = (vx0 && vy0) ? wx0 * wy0 : 0.0f;
        w.y = (vx1 && vy0) ? wx1 * wy0 : 0.0f;
        w.z = (vx0 && vy1) ? wx0 * wy1 : 0.0f;
        w.w = (vx1 && vy1) ? wx1 * wy1 : 0.0f;
        s_w4[tid] = w;
    }
    __syncthreads();

    // ---- Phase B: predicated gathers + bilinear combine (float4 channels) ----
    // Store swizzled: row p, float4-col (g ^ (p4&7)), components rotated by 2*(p4>>3)
    const float4* fT = (const float4*)(g_featT + (size_t)b * PIX * CQ);
    #pragma unroll
    for (int it = 0; it < ITEMS / THREADS; it++) {
        int i = it * THREADS + tid;   // 0..1279
        int p = i / CG;
        int g = i - p * CG;
        float4 w = s_w4[p];
        int4 id = s_idx4[p];
        float4 a = make_float4(0.f, 0.f, 0.f, 0.f);
        if (w.x != 0.0f) {
            float4 v = __ldg(&fT[id.x + g]);
            a.x += w.x * v.x; a.y += w.x * v.y; a.z += w.x * v.z; a.w += w.x * v.w;
        }
        if (w.y != 0.0f) {
            float4 v = __ldg(&fT[id.y + g]);
            a.x += w.y * v.x; a.y += w.y * v.y; a.z += w.y * v.z; a.w += w.y * v.w;
        }
        if (w.z != 0.0f) {
            float4 v = __ldg(&fT[id.z + g]);
            a.x += w.z * v.x; a.y += w.z * v.y; a.z += w.z * v.z; a.w += w.z * v.w;
        }
        if (w.w != 0.0f) {
            float4 v = __ldg(&fT[id.w + g]);
            a.x += w.w * v.x; a.y += w.w * v.y; a.z += w.w * v.z; a.w += w.w * v.w;
        }
        int p4 = p >> 2;
        int G = p4 & 7;
        float4 st = ((p4 & 8) != 0) ? make_float4(a.z, a.w, a.x, a.y) : a;
        s_out4[p * SROW4 + (g ^ G)] = st;
    }
    __syncthreads();

    // ---- Phase C: conflict-free scalar LDS column reads + coalesced STG.128 ----
    {
        const float* s_outf = (const float*)s_out4;
        float4* out4 = (float4*)out;
        #pragma unroll
        for (int it = 0; it < ITEMS / THREADS; it++) {
            int i = it * THREADS + tid;   // 0..1279
            int c = i >> 4;               // channel 0..79
            int p4 = i & 15;              // point-quad 0..15
            int G = p4 & 7;
            int rx = p4 >> 3;             // 0 or 1
            int col4 = (c >> 2) ^ G;
            int comp = (c + 2 * rx) & 3;  // de-rotate component
            int base = (4 * p4) * (SROW4 * 4) + col4 * 4 + comp;
            float4 r;
            r.x = s_outf[base + 0 * (SROW4 * 4)];
            r.y = s_outf[base + 1 * (SROW4 * 4)];
            r.z = s_outf[base + 2 * (SROW4 * 4)];
            r.w = s_outf[base + 3 * (SROW4 * 4)];
            size_t idx = (size_t)(b * CQ + c) * (NPTS / 4) + (nbase >> 2) + p4;
            out4[idx] = r;
        }
    }
}

extern "C" void kernel_launch(void* const* d_in, const int* in_sizes, int n_in,
                              void* d_out, int out_size) {
    const float* img_feats = (const float*)d_in[0];
    const float* intrin    = (const float*)d_in[1];
    const float* extrin    = (const float*)d_in[2];
    const float* bda       = (const float*)d_in[3];
    float* out = (float*)d_out;

    dim3 tgrid((PIX + 31) / 32, (CQ + 31) / 32, BQ);
    prep_kernel<<<tgrid, dim3(32, 8)>>>(img_feats, intrin, extrin, bda);

    int nblocks = BQ * (NPTS / PTS_PER_BLK);   // 8192
    bev_kernel<<<nblocks, THREADS>>>(out);
}

// round 5
// speedup vs baseline: 1.6964x; 1.0476x over previous
#include <cuda_runtime.h>
#include <cuda_fp16.h>
#include <math.h>

#define BQ 2
#define CQ 80
#define HQ 32
#define WQ 88
#define PIX (HQ * WQ)          // 2816 pixels
#define NPTS 262144            // 128*128*16 points per batch
#define PTS_PER_BLK 64
#define THREADS 256
#define CG 20                  // 80 channels = 20 groups of 4
#define ITEMS (PTS_PER_BLK * CG)   // 1280 work items per block
#define SROW4 24               // s_out row stride in float4 (96 floats = 0 mod 32 banks)

// Transposed features in fp16: (B, H*W, C), 4 channels per uint2 (8B).
__device__ uint2 g_featTh[BQ * PIX * CG];
// Combined 3x4 projection matrix per batch: F = (intr*scale) * extr * bda
__device__ float g_F[BQ][12];

// ---------------- prep: tiled transpose (B,C,HW) -> (B,HW,C) fp16 + matrices ----------------
__global__ void prep_kernel(const float* __restrict__ feat,
                            const float* __restrict__ intrin,
                            const float* __restrict__ extrin,
                            const float* __restrict__ bda) {
    __shared__ float tile[32][33];
    if (blockIdx.x == 0 && blockIdx.y == 0 && blockIdx.z == 0 &&
        threadIdx.y == 0 && threadIdx.x < BQ) {
        int b = threadIdx.x;
        const float* In = intrin + b * 16;
        const float* Ex = extrin + b * 16;
        const float* Bd = bda + b * 16;
        float P[3][4];
        for (int r = 0; r < 3; r++) {
            float s = (r < 2) ? 0.125f : 1.0f;
            for (int cc = 0; cc < 4; cc++) {
                float acc = 0.0f;
                for (int k = 0; k < 3; k++)
                    acc += In[r * 4 + k] * s * Ex[k * 4 + cc];
                P[r][cc] = acc;
            }
        }
        for (int r = 0; r < 3; r++)
            for (int cc = 0; cc < 4; cc++) {
                float acc = 0.0f;
                for (int k = 0; k < 4; k++)
                    acc += P[r][k] * Bd[k * 4 + cc];
                g_F[b][r * 4 + cc] = acc;
            }
    }
    int b = blockIdx.z;
    int ct = blockIdx.y * 32;
    int pt = blockIdx.x * 32;
    int tx = threadIdx.x, ty = threadIdx.y;   // (32,8)
    const float* src = feat + (size_t)b * CQ * PIX;
    #pragma unroll
    for (int j = 0; j < 32; j += 8) {
        int c = ct + ty + j;
        int p = pt + tx;
        if (c < CQ && p < PIX)
            tile[ty + j][tx] = src[(size_t)c * PIX + p];
    }
    __syncthreads();
    __half* dst = (__half*)g_featTh;
    dst += (size_t)b * PIX * CQ;
    #pragma unroll
    for (int j = 0; j < 32; j += 8) {
        int p = pt + ty + j;
        int c = ct + tx;
        if (c < CQ && p < PIX)
            dst[(size_t)p * CQ + c] = __float2half(tile[tx][ty + j]);
    }
}

// ---------------- main kernel ----------------
__global__ void __launch_bounds__(THREADS)
bev_kernel(float* __restrict__ out) {
    __shared__ float4 s_w4[PTS_PER_BLK];
    __shared__ int4   s_idx4[PTS_PER_BLK];          // pixel * CG (group base)
    __shared__ float4 s_out4[PTS_PER_BLK * SROW4];  // 64 rows x 24 float4 (swizzled)

    const int bidx = blockIdx.x;
    const int b = bidx >> 12;                 // 4096 blocks per batch
    const int nbase = (bidx & 4095) * PTS_PER_BLK;
    const int tid = threadIdx.x;

    // ---- Phase A: geometry for 64 points ----
    if (tid < PTS_PER_BLK) {
        int n = nbase + tid;
        int ix = n >> 11;            // NY*NZ = 2048
        int iy = (n >> 4) & 127;     // NZ = 16
        int iz = n & 15;
        float X = -51.2f + ix * 0.8f;
        float Y = -51.2f + iy * 0.8f;
        float Z = -5.0f + iz * 0.5f;
        const float* F = g_F[b];
        float px = F[0] * X + F[1] * Y + F[2]  * Z + F[3];
        float py = F[4] * X + F[5] * Y + F[6]  * Z + F[7];
        float pz = F[8] * X + F[9] * Y + F[10] * Z + F[11];
        float u = px / pz;
        float v = py / pz;
        u = u / (float)WQ * 2.0f - 1.0f;
        v = v / (float)HQ * 2.0f - 1.0f;
        float x = (u + 1.0f) * 0.5f * (float)(WQ - 1);
        float y = (v + 1.0f) * 0.5f * (float)(HQ - 1);
        if (!(isfinite(x) && isfinite(y))) { x = -10.0f; y = -10.0f; }
        float x0f = floorf(x), y0f = floorf(y);
        float wx1 = x - x0f, wy1 = y - y0f;
        float wx0 = 1.0f - wx1, wy0 = 1.0f - wy1;
        float x1f = x0f + 1.0f, y1f = y0f + 1.0f;
        bool vx0 = (x0f >= 0.0f) && (x0f <= (float)(WQ - 1));
        bool vx1 = (x1f >= 0.0f) && (x1f <= (float)(WQ - 1));
        bool vy0 = (y0f >= 0.0f) && (y0f <= (float)(HQ - 1));
        bool vy1 = (y1f >= 0.0f) && (y1f <= (float)(HQ - 1));
        int xi0 = (int)fminf(fmaxf(x0f, 0.0f), (float)(WQ - 1));
        int xi1 = (int)fminf(fmaxf(x1f, 0.0f), (float)(WQ - 1));
        int yi0 = (int)fminf(fmaxf(y0f, 0.0f), (float)(HQ - 1));
        int yi1 = (int)fminf(fmaxf(y1f, 0.0f), (float)(HQ - 1));
        int4 id;
        id.x = (yi0 * WQ + xi0) * CG;
        id.y = (yi0 * WQ + xi1) * CG;
        id.z = (yi1 * WQ + xi0) * CG;
        id.w = (yi1 * WQ + xi1) * CG;
        s_idx4[tid] = id;
        float4 w;
        w.x = (vx0 && vy0) ? wx0 * wy0 : 0.0f;
        w.y = (vx1 && vy0) ? wx1 * wy0 : 0.0f;
        w.z = (vx0 && vy1) ? wx0 * wy1 : 0.0f;
        w.w = (vx1 && vy1) ? wx1 * wy1 : 0.0f;
        s_w4[tid] = w;
    }
    __syncthreads();

    // ---- Phase B: predicated fp16 gathers + f32 bilinear combine ----
    const uint2* fT = g_featTh + (size_t)b * PIX * CG;
    #pragma unroll
    for (int it = 0; it < ITEMS / THREADS; it++) {
        int i = it * THREADS + tid;   // 0..1279
        int p = i / CG;
        int g = i - p * CG;
        float4 w = s_w4[p];
        int4 id = s_idx4[p];
        float4 a = make_float4(0.f, 0.f, 0.f, 0.f);
        if (w.x != 0.0f) {
            uint2 raw = __ldg(&fT[id.x + g]);
            float2 f0 = __half22float2(*reinterpret_cast<__half2*>(&raw.x));
            float2 f1 = __half22float2(*reinterpret_cast<__half2*>(&raw.y));
            a.x += w.x * f0.x; a.y += w.x * f0.y; a.z += w.x * f1.x; a.w += w.x * f1.y;
        }
        if (w.y != 0.0f) {
            uint2 raw = __ldg(&fT[id.y + g]);
            float2 f0 = __half22float2(*reinterpret_cast<__half2*>(&raw.x));
            float2 f1 = __half22float2(*reinterpret_cast<__half2*>(&raw.y));
            a.x += w.y * f0.x; a.y += w.y * f0.y; a.z += w.y * f1.x; a.w += w.y * f1.y;
        }
        if (w.z != 0.0f) {
            uint2 raw = __ldg(&fT[id.z + g]);
            float2 f0 = __half22float2(*reinterpret_cast<__half2*>(&raw.x));
            float2 f1 = __half22float2(*reinterpret_cast<__half2*>(&raw.y));
            a.x += w.z * f0.x; a.y += w.z * f0.y; a.z += w.z * f1.x; a.w += w.z * f1.y;
        }
        if (w.w != 0.0f) {
            uint2 raw = __ldg(&fT[id.w + g]);
            float2 f0 = __half22float2(*reinterpret_cast<__half2*>(&raw.x));
            float2 f1 = __half22float2(*reinterpret_cast<__half2*>(&raw.y));
            a.x += w.w * f0.x; a.y += w.w * f0.y; a.z += w.w * f1.x; a.w += w.w * f1.y;
        }
        int p4 = p >> 2;
        int G = p4 & 7;
        float4 st = ((p4 & 8) != 0) ? make_float4(a.z, a.w, a.x, a.y) : a;
        s_out4[p * SROW4 + (g ^ G)] = st;
    }
    __syncthreads();

    // ---- Phase C: conflict-free scalar LDS column reads + coalesced STG.128 ----
    {
        const float* s_outf = (const float*)s_out4;
        float4* out4 = (float4*)out;
        #pragma unroll
        for (int it = 0; it < ITEMS / THREADS; it++) {
            int i = it * THREADS + tid;   // 0..1279
            int c = i >> 4;               // channel 0..79
            int p4 = i & 15;              // point-quad 0..15
            int G = p4 & 7;
            int rx = p4 >> 3;             // 0 or 1
            int col4 = (c >> 2) ^ G;
            int comp = (c + 2 * rx) & 3;  // de-rotate component
            int base = (4 * p4) * (SROW4 * 4) + col4 * 4 + comp;
            float4 r;
            r.x = s_outf[base + 0 * (SROW4 * 4)];
            r.y = s_outf[base + 1 * (SROW4 * 4)];
            r.z = s_outf[base + 2 * (SROW4 * 4)];
            r.w = s_outf[base + 3 * (SROW4 * 4)];
            size_t idx = (size_t)(b * CQ + c) * (NPTS / 4) + (nbase >> 2) + p4;
            out4[idx] = r;
        }
    }
}

extern "C" void kernel_launch(void* const* d_in, const int* in_sizes, int n_in,
                              void* d_out, int out_size) {
    const float* img_feats = (const float*)d_in[0];
    const float* intrin    = (const float*)d_in[1];
    const float* extrin    = (const float*)d_in[2];
    const float* bda       = (const float*)d_in[3];
    float* out = (float*)d_out;

    dim3 tgrid((PIX + 31) / 32, (CQ + 31) / 32, BQ);
    prep_kernel<<<tgrid, dim3(32, 8)>>>(img_feats, intrin, extrin, bda);

    int nblocks = BQ * (NPTS / PTS_PER_BLK);   // 8192
    bev_kernel<<<nblocks, THREADS>>>(out);
}

// round 6
// speedup vs baseline: 1.7611x; 1.0381x over previous
#include <cuda_runtime.h>
#include <cuda_fp16.h>
#include <math.h>

#define BQ 2
#define CQ 80
#define HQ 32
#define WQ 88
#define PIX (HQ * WQ)          // 2816 pixels
#define NPTS 262144            // 128*128*16 points per batch
#define PTS_PER_BLK 64
#define THREADS 256
#define NG8 10                 // 80 channels = 10 groups of 8 (uint4 of halves)
#define ITEMS8 (PTS_PER_BLK * NG8)   // 640 gather items per block
#define ITEMSC (PTS_PER_BLK / 4 * CQ) // 1280 store items per block
#define SROW4 24               // s_out row stride in float4 (96 floats = 0 mod 32 banks)

// Transposed features in fp16: (B, H*W, C), 8 channels per uint4 (16B).
__device__ uint4 g_featTh[BQ * PIX * NG8];
// Combined 3x4 projection matrix per batch: F = (intr*scale) * extr * bda
__device__ float g_F[BQ][12];

// ---------------- prep: tiled transpose (B,C,HW) -> (B,HW,C) fp16 + matrices ----------------
__global__ void prep_kernel(const float* __restrict__ feat,
                            const float* __restrict__ intrin,
                            const float* __restrict__ extrin,
                            const float* __restrict__ bda) {
    __shared__ float tile[32][33];
    if (blockIdx.x == 0 && blockIdx.y == 0 && blockIdx.z == 0 &&
        threadIdx.y == 0 && threadIdx.x < BQ) {
        int b = threadIdx.x;
        const float* In = intrin + b * 16;
        const float* Ex = extrin + b * 16;
        const float* Bd = bda + b * 16;
        float P[3][4];
        for (int r = 0; r < 3; r++) {
            float s = (r < 2) ? 0.125f : 1.0f;
            for (int cc = 0; cc < 4; cc++) {
                float acc = 0.0f;
                for (int k = 0; k < 3; k++)
                    acc += In[r * 4 + k] * s * Ex[k * 4 + cc];
                P[r][cc] = acc;
            }
        }
        for (int r = 0; r < 3; r++)
            for (int cc = 0; cc < 4; cc++) {
                float acc = 0.0f;
                for (int k = 0; k < 4; k++)
                    acc += P[r][k] * Bd[k * 4 + cc];
                g_F[b][r * 4 + cc] = acc;
            }
    }
    int b = blockIdx.z;
    int ct = blockIdx.y * 32;
    int pt = blockIdx.x * 32;
    int tx = threadIdx.x, ty = threadIdx.y;   // (32,8)
    const float* src = feat + (size_t)b * CQ * PIX;
    #pragma unroll
    for (int j = 0; j < 32; j += 8) {
        int c = ct + ty + j;
        int p = pt + tx;
        if (c < CQ && p < PIX)
            tile[ty + j][tx] = src[(size_t)c * PIX + p];
    }
    __syncthreads();
    __half* dst = (__half*)g_featTh;
    dst += (size_t)b * PIX * CQ;
    #pragma unroll
    for (int j = 0; j < 32; j += 8) {
        int p = pt + ty + j;
        int c = ct + tx;
        if (c < CQ && p < PIX)
            dst[(size_t)p * CQ + c] = __float2half(tile[tx][ty + j]);
    }
}

// ---------------- main kernel ----------------
__global__ void __launch_bounds__(THREADS)
bev_kernel(float* __restrict__ out) {
    __shared__ float4 s_w4[PTS_PER_BLK];
    __shared__ int4   s_idx4[PTS_PER_BLK];          // pixel * NG8 (uint4 group base)
    __shared__ float4 s_out4[PTS_PER_BLK * SROW4];  // 64 rows x 24 float4 (swizzled)

    const int bidx = blockIdx.x;
    const int b = bidx >> 12;                 // 4096 blocks per batch
    const int nbase = (bidx & 4095) * PTS_PER_BLK;
    const int tid = threadIdx.x;

    // ---- Phase A: geometry for 64 points ----
    if (tid < PTS_PER_BLK) {
        int n = nbase + tid;
        int ix = n >> 11;            // NY*NZ = 2048
        int iy = (n >> 4) & 127;     // NZ = 16
        int iz = n & 15;
        float X = -51.2f + ix * 0.8f;
        float Y = -51.2f + iy * 0.8f;
        float Z = -5.0f + iz * 0.5f;
        const float* F = g_F[b];
        float px = F[0] * X + F[1] * Y + F[2]  * Z + F[3];
        float py = F[4] * X + F[5] * Y + F[6]  * Z + F[7];
        float pz = F[8] * X + F[9] * Y + F[10] * Z + F[11];
        float u = px / pz;
        float v = py / pz;
        u = u / (float)WQ * 2.0f - 1.0f;
        v = v / (float)HQ * 2.0f - 1.0f;
        float x = (u + 1.0f) * 0.5f * (float)(WQ - 1);
        float y = (v + 1.0f) * 0.5f * (float)(HQ - 1);
        if (!(isfinite(x) && isfinite(y))) { x = -10.0f; y = -10.0f; }
        float x0f = floorf(x), y0f = floorf(y);
        float wx1 = x - x0f, wy1 = y - y0f;
        float wx0 = 1.0f - wx1, wy0 = 1.0f - wy1;
        float x1f = x0f + 1.0f, y1f = y0f + 1.0f;
        bool vx0 = (x0f >= 0.0f) && (x0f <= (float)(WQ - 1));
        bool vx1 = (x1f >= 0.0f) && (x1f <= (float)(WQ - 1));
        bool vy0 = (y0f >= 0.0f) && (y0f <= (float)(HQ - 1));
        bool vy1 = (y1f >= 0.0f) && (y1f <= (float)(HQ - 1));
        int xi0 = (int)fminf(fmaxf(x0f, 0.0f), (float)(WQ - 1));
        int xi1 = (int)fminf(fmaxf(x1f, 0.0f), (float)(WQ - 1));
        int yi0 = (int)fminf(fmaxf(y0f, 0.0f), (float)(HQ - 1));
        int yi1 = (int)fminf(fmaxf(y1f, 0.0f), (float)(HQ - 1));
        int4 id;
        id.x = (yi0 * WQ + xi0) * NG8;
        id.y = (yi0 * WQ + xi1) * NG8;
        id.z = (yi1 * WQ + xi0) * NG8;
        id.w = (yi1 * WQ + xi1) * NG8;
        s_idx4[tid] = id;
        float4 w;
        w.x = (vx0 && vy0) ? wx0 * wy0 : 0.0f;
        w.y = (vx1 && vy0) ? wx1 * wy0 : 0.0f;
        w.z = (vx0 && vy1) ? wx0 * wy1 : 0.0f;
        w.w = (vx1 && vy1) ? wx1 * wy1 : 0.0f;
        s_w4[tid] = w;
    }
    __syncthreads();

    // ---- Phase B: predicated fp16 LDG.128 gathers (8 channels) + f32 combine ----
    const uint4* fT = g_featTh + (size_t)b * PIX * NG8;
    #pragma unroll
    for (int it = 0; it < 3; it++) {
        int i = it * THREADS + tid;   // 0..767, valid < 640
        if (i < ITEMS8) {
            int p = i / NG8;
            int g = i - p * NG8;
            float4 w = s_w4[p];
            int4 id = s_idx4[p];
            float a0 = 0.f, a1 = 0.f, a2 = 0.f, a3 = 0.f;
            float a4 = 0.f, a5 = 0.f, a6 = 0.f, a7 = 0.f;
            #define CORNER(WK, IDK)                                              \
                if (WK != 0.0f) {                                                \
                    uint4 raw = __ldg(&fT[IDK + g]);                             \
                    float2 f0 = __half22float2(*reinterpret_cast<__half2*>(&raw.x)); \
                    float2 f1 = __half22float2(*reinterpret_cast<__half2*>(&raw.y)); \
                    float2 f2 = __half22float2(*reinterpret_cast<__half2*>(&raw.z)); \
                    float2 f3 = __half22float2(*reinterpret_cast<__half2*>(&raw.w)); \
                    a0 += WK * f0.x; a1 += WK * f0.y; a2 += WK * f1.x; a3 += WK * f1.y; \
                    a4 += WK * f2.x; a5 += WK * f2.y; a6 += WK * f3.x; a7 += WK * f3.y; \
                }
            CORNER(w.x, id.x)
            CORNER(w.y, id.y)
            CORNER(w.z, id.z)
            CORNER(w.w, id.w)
            #undef CORNER
            int p4 = p >> 2;
            int G = p4 & 7;
            bool rot = (p4 & 8) != 0;
            float4 lo = rot ? make_float4(a2, a3, a0, a1) : make_float4(a0, a1, a2, a3);
            float4 hi = rot ? make_float4(a6, a7, a4, a5) : make_float4(a4, a5, a6, a7);
            s_out4[p * SROW4 + ((2 * g) ^ G)] = lo;
            s_out4[p * SROW4 + ((2 * g + 1) ^ G)] = hi;
        }
    }
    __syncthreads();

    // ---- Phase C: conflict-free scalar LDS column reads + coalesced STG.128 ----
    {
        const float* s_outf = (const float*)s_out4;
        float4* out4 = (float4*)out;
        #pragma unroll
        for (int it = 0; it < ITEMSC / THREADS; it++) {
            int i = it * THREADS + tid;   // 0..1279
            int c = i >> 4;               // channel 0..79
            int p4 = i & 15;              // point-quad 0..15
            int G = p4 & 7;
            int rx = p4 >> 3;             // 0 or 1
            int col4 = (c >> 2) ^ G;
            int comp = (c + 2 * rx) & 3;  // de-rotate component
            int base = (4 * p4) * (SROW4 * 4) + col4 * 4 + comp;
            float4 r;
            r.x = s_outf[base + 0 * (SROW4 * 4)];
            r.y = s_outf[base + 1 * (SROW4 * 4)];
            r.z = s_outf[base + 2 * (SROW4 * 4)];
            r.w = s_outf[base + 3 * (SROW4 * 4)];
            size_t idx = (size_t)(b * CQ + c) * (NPTS / 4) + (nbase >> 2) + p4;
            out4[idx] = r;
        }
    }
}

extern "C" void kernel_launch(void* const* d_in, const int* in_sizes, int n_in,
                              void* d_out, int out_size) {
    const float* img_feats = (const float*)d_in[0];
    const float* intrin    = (const float*)d_in[1];
    const float* extrin    = (const float*)d_in[2];
    const float* bda       = (const float*)d_in[3];
    float* out = (float*)d_out;

    dim3 tgrid((PIX + 31) / 32, (CQ + 31) / 32, BQ);
    prep_kernel<<<tgrid, dim3(32, 8)>>>(img_feats, intrin, extrin, bda);

    int nblocks = BQ * (NPTS / PTS_PER_BLK);   // 8192
    bev_kernel<<<nblocks, THREADS>>>(out);
}

// round 7
// speedup vs baseline: 1.9986x; 1.1348x over previous
#include <cuda_runtime.h>
#include <cuda_fp16.h>
#include <math.h>

#define BQ 2
#define CQ 80
#define HQ 32
#define WQ 88
#define PIX (HQ * WQ)          // 2816 pixels
#define NPTS 262144            // 128*128*16 points per batch
#define PTS_PER_BLK 64
#define THREADS 256
#define NG8 10                 // 80 channels = 10 groups of 8 (uint4 of halves)
#define FROW 12                // feature row stride in uint4 (192B, padded from 160B)
#define ITEMS8 (PTS_PER_BLK * NG8)      // 640 gather items per block
#define ITEMSC (PTS_PER_BLK / 4 * 40)   // 640 store items (channel-pair x point-quad)
#define SROWU 64               // staging row stride in uints (16 uint4 = 256B, 0 mod 32 banks)

// Transposed features in fp16: (B, H*W, Cpad), 8 channels per uint4, 12 uint4/pixel.
__device__ uint4 g_featTh[BQ * PIX * FROW];
// Combined 3x4 projection matrix per batch: F = (intr*scale) * extr * bda
__device__ float g_F[BQ][12];

// ---------------- prep: tiled transpose (B,C,HW) -> (B,HW,Cpad) fp16 + matrices ----------------
__global__ void prep_kernel(const float* __restrict__ feat,
                            const float* __restrict__ intrin,
                            const float* __restrict__ extrin,
                            const float* __restrict__ bda) {
    __shared__ float tile[32][33];
    if (blockIdx.x == 0 && blockIdx.y == 0 && blockIdx.z == 0 &&
        threadIdx.y == 0 && threadIdx.x < BQ) {
        int b = threadIdx.x;
        const float* In = intrin + b * 16;
        const float* Ex = extrin + b * 16;
        const float* Bd = bda + b * 16;
        float P[3][4];
        for (int r = 0; r < 3; r++) {
            float s = (r < 2) ? 0.125f : 1.0f;
            for (int cc = 0; cc < 4; cc++) {
                float acc = 0.0f;
                for (int k = 0; k < 3; k++)
                    acc += In[r * 4 + k] * s * Ex[k * 4 + cc];
                P[r][cc] = acc;
            }
        }
        for (int r = 0; r < 3; r++)
            for (int cc = 0; cc < 4; cc++) {
                float acc = 0.0f;
                for (int k = 0; k < 4; k++)
                    acc += P[r][k] * Bd[k * 4 + cc];
                g_F[b][r * 4 + cc] = acc;
            }
    }
    int b = blockIdx.z;
    int ct = blockIdx.y * 32;
    int pt = blockIdx.x * 32;
    int tx = threadIdx.x, ty = threadIdx.y;   // (32,8)
    const float* src = feat + (size_t)b * CQ * PIX;
    #pragma unroll
    for (int j = 0; j < 32; j += 8) {
        int c = ct + ty + j;
        int p = pt + tx;
        if (c < CQ && p < PIX)
            tile[ty + j][tx] = src[(size_t)c * PIX + p];
    }
    __syncthreads();
    __half* dst = (__half*)g_featTh;
    dst += (size_t)b * PIX * (FROW * 8);
    #pragma unroll
    for (int j = 0; j < 32; j += 8) {
        int p = pt + ty + j;
        int c = ct + tx;
        if (c < CQ && p < PIX)
            dst[(size_t)p * (FROW * 8) + c] = __float2half(tile[tx][ty + j]);
    }
}

// ---------------- main kernel ----------------
__global__ void __launch_bounds__(THREADS)
bev_kernel(float* __restrict__ out) {
    __shared__ float4 s_w4[PTS_PER_BLK];
    __shared__ int4   s_idx4[PTS_PER_BLK];              // pixel * FROW (uint4 base)
    __shared__ uint4  s_stg[PTS_PER_BLK * (SROWU / 4)]; // 64 rows x 16 uint4 (fp16, swizzled)

    const int bidx = blockIdx.x;
    const int b = bidx >> 12;                 // 4096 blocks per batch
    const int nbase = (bidx & 4095) * PTS_PER_BLK;
    const int tid = threadIdx.x;

    // ---- Phase A: geometry for 64 points ----
    if (tid < PTS_PER_BLK) {
        int n = nbase + tid;
        int ix = n >> 11;            // NY*NZ = 2048
        int iy = (n >> 4) & 127;     // NZ = 16
        int iz = n & 15;
        float X = -51.2f + ix * 0.8f;
        float Y = -51.2f + iy * 0.8f;
        float Z = -5.0f + iz * 0.5f;
        const float* F = g_F[b];
        float px = F[0] * X + F[1] * Y + F[2]  * Z + F[3];
        float py = F[4] * X + F[5] * Y + F[6]  * Z + F[7];
        float pz = F[8] * X + F[9] * Y + F[10] * Z + F[11];
        float u = px / pz;
        float v = py / pz;
        u = u / (float)WQ * 2.0f - 1.0f;
        v = v / (float)HQ * 2.0f - 1.0f;
        float x = (u + 1.0f) * 0.5f * (float)(WQ - 1);
        float y = (v + 1.0f) * 0.5f * (float)(HQ - 1);
        if (!(isfinite(x) && isfinite(y))) { x = -10.0f; y = -10.0f; }
        float x0f = floorf(x), y0f = floorf(y);
        float wx1 = x - x0f, wy1 = y - y0f;
        float wx0 = 1.0f - wx1, wy0 = 1.0f - wy1;
        float x1f = x0f + 1.0f, y1f = y0f + 1.0f;
        bool vx0 = (x0f >= 0.0f) && (x0f <= (float)(WQ - 1));
        bool vx1 = (x1f >= 0.0f) && (x1f <= (float)(WQ - 1));
        bool vy0 = (y0f >= 0.0f) && (y0f <= (float)(HQ - 1));
        bool vy1 = (y1f >= 0.0f) && (y1f <= (float)(HQ - 1));
        int xi0 = (int)fminf(fmaxf(x0f, 0.0f), (float)(WQ - 1));
        int xi1 = (int)fminf(fmaxf(x1f, 0.0f), (float)(WQ - 1));
        int yi0 = (int)fminf(fmaxf(y0f, 0.0f), (float)(HQ - 1));
        int yi1 = (int)fminf(fmaxf(y1f, 0.0f), (float)(HQ - 1));
        int4 id;
        id.x = (yi0 * WQ + xi0) * FROW;
        id.y = (yi0 * WQ + xi1) * FROW;
        id.z = (yi1 * WQ + xi0) * FROW;
        id.w = (yi1 * WQ + xi1) * FROW;
        s_idx4[tid] = id;
        float4 w;
        w.x = (vx0 && vy0) ? wx0 * wy0 : 0.0f;
        w.y = (vx1 && vy0) ? wx1 * wy0 : 0.0f;
        w.z = (vx0 && vy1) ? wx0 * wy1 : 0.0f;
        w.w = (vx1 && vy1) ? wx1 * wy1 : 0.0f;
        s_w4[tid] = w;
    }
    __syncthreads();

    // ---- Phase B: predicated fp16 LDG.128 gathers (8 ch) + f32 combine -> fp16 staging ----
    const uint4* fT = g_featTh + (size_t)b * PIX * FROW;
    #pragma unroll
    for (int it = 0; it < 3; it++) {
        int i = it * THREADS + tid;   // 0..767, valid < 640
        if (i < ITEMS8) {
            int p = i / NG8;
            int g = i - p * NG8;
            float4 w = s_w4[p];
            int4 id = s_idx4[p];
            float a0 = 0.f, a1 = 0.f, a2 = 0.f, a3 = 0.f;
            float a4 = 0.f, a5 = 0.f, a6 = 0.f, a7 = 0.f;
            #define CORNER(WK, IDK)                                              \
                if (WK != 0.0f) {                                                \
                    uint4 raw = __ldg(&fT[IDK + g]);                             \
                    float2 f0 = __half22float2(*reinterpret_cast<__half2*>(&raw.x)); \
                    float2 f1 = __half22float2(*reinterpret_cast<__half2*>(&raw.y)); \
                    float2 f2 = __half22float2(*reinterpret_cast<__half2*>(&raw.z)); \
                    float2 f3 = __half22float2(*reinterpret_cast<__half2*>(&raw.w)); \
                    a0 += WK * f0.x; a1 += WK * f0.y; a2 += WK * f1.x; a3 += WK * f1.y; \
                    a4 += WK * f2.x; a5 += WK * f2.y; a6 += WK * f3.x; a7 += WK * f3.y; \
                }
            CORNER(w.x, id.x)
            CORNER(w.y, id.y)
            CORNER(w.z, id.z)
            CORNER(w.w, id.w)
            #undef CORNER
            __half2 h0 = __floats2half2_rn(a0, a1);
            __half2 h1 = __floats2half2_rn(a2, a3);
            __half2 h2 = __floats2half2_rn(a4, a5);
            __half2 h3 = __floats2half2_rn(a6, a7);
            uint4 st;
            st.x = *reinterpret_cast<unsigned*>(&h0);
            st.y = *reinterpret_cast<unsigned*>(&h1);
            st.z = *reinterpret_cast<unsigned*>(&h2);
            st.w = *reinterpret_cast<unsigned*>(&h3);
            int p4 = p >> 2;
            int G = p4 & 7;
            if ((p4 & 8) != 0) st = make_uint4(st.z, st.w, st.x, st.y);
            s_stg[p * (SROWU / 4) + (g ^ G)] = st;
        }
    }
    __syncthreads();

    // ---- Phase C: conflict-free LDS.32 (half2 = channel pair) + 2x coalesced STG.128 ----
    {
        const unsigned* s_u = (const unsigned*)s_stg;
        float4* out4 = (float4*)out;
        #pragma unroll
        for (int it = 0; it < 3; it++) {
            int i = it * THREADS + tid;   // 0..767, valid < 640
            if (i < ITEMSC) {
                int cp = i >> 4;              // channel-pair 0..39
                int p4 = i & 15;              // point-quad 0..15
                int G = p4 & 7;
                int rx = p4 >> 3;
                int word = 4 * ((cp >> 2) ^ G) + ((cp + 2 * rx) & 3);
                int base = (4 * p4) * SROWU + word;
                unsigned u0 = s_u[base + 0 * SROWU];
                unsigned u1 = s_u[base + 1 * SROWU];
                unsigned u2 = s_u[base + 2 * SROWU];
                unsigned u3 = s_u[base + 3 * SROWU];
                float2 f0 = __half22float2(*reinterpret_cast<__half2*>(&u0));
                float2 f1 = __half22float2(*reinterpret_cast<__half2*>(&u1));
                float2 f2 = __half22float2(*reinterpret_cast<__half2*>(&u2));
                float2 f3 = __half22float2(*reinterpret_cast<__half2*>(&u3));
                int c0 = 2 * cp;
                size_t idx0 = (size_t)(b * CQ + c0) * (NPTS / 4) + (nbase >> 2) + p4;
                size_t idx1 = idx0 + (NPTS / 4);
                out4[idx0] = make_float4(f0.x, f1.x, f2.x, f3.x);
                out4[idx1] = make_float4(f0.y, f1.y, f2.y, f3.y);
            }
        }
    }
}

extern "C" void kernel_launch(void* const* d_in, const int* in_sizes, int n_in,
                              void* d_out, int out_size) {
    const float* img_feats = (const float*)d_in[0];
    const float* intrin    = (const float*)d_in[1];
    const float* extrin    = (const float*)d_in[2];
    const float* bda       = (const float*)d_in[3];
    float* out = (float*)d_out;

    dim3 tgrid((PIX + 31) / 32, (CQ + 31) / 32, BQ);
    prep_kernel<<<tgrid, dim3(32, 8)>>>(img_feats, intrin, extrin, bda);

    int nblocks = BQ * (NPTS / PTS_PER_BLK);   // 8192
    bev_kernel<<<nblocks, THREADS>>>(out);
}

// round 8
// speedup vs baseline: 2.0000x; 1.0007x over previous
#include <cuda_runtime.h>
#include <cuda_fp16.h>
#include <math.h>

#define BQ 2
#define CQ 80
#define HQ 32
#define WQ 88
#define PIX (HQ * WQ)          // 2816 pixels
#define NPTS 262144            // 128*128*16 points per batch
#define PTS_PER_BLK 64
#define THREADS 320
#define NG8 10                 // 80 channels = 10 groups of 8 (uint4 of halves)
#define FROW 12                // feature row stride in uint4 (192B, padded from 160B)
#define ITEMS8 (PTS_PER_BLK * NG8)      // 640 gather items per block
#define ITEMSC (PTS_PER_BLK / 4 * 40)   // 640 store items (channel-pair x point-quad)
#define SROWU 64               // staging row stride in uints (16 uint4 = 256B, 0 mod 32 banks)

// Transposed features in fp16: (B, H*W, Cpad), 8 channels per uint4, 12 uint4/pixel.
__device__ uint4 g_featTh[BQ * PIX * FROW];
// Combined 3x4 projection matrix per batch: F = (intr*scale) * extr * bda
__device__ float g_F[BQ][12];

// ---------------- prep: tiled transpose (B,C,HW) -> (B,HW,Cpad) fp16 + matrices ----------------
__global__ void prep_kernel(const float* __restrict__ feat,
                            const float* __restrict__ intrin,
                            const float* __restrict__ extrin,
                            const float* __restrict__ bda) {
    __shared__ float tile[32][33];
    if (blockIdx.x == 0 && blockIdx.y == 0 && blockIdx.z == 0 &&
        threadIdx.y == 0 && threadIdx.x < BQ) {
        int b = threadIdx.x;
        const float* In = intrin + b * 16;
        const float* Ex = extrin + b * 16;
        const float* Bd = bda + b * 16;
        float P[3][4];
        for (int r = 0; r < 3; r++) {
            float s = (r < 2) ? 0.125f : 1.0f;
            for (int cc = 0; cc < 4; cc++) {
                float acc = 0.0f;
                for (int k = 0; k < 3; k++)
                    acc += In[r * 4 + k] * s * Ex[k * 4 + cc];
                P[r][cc] = acc;
            }
        }
        for (int r = 0; r < 3; r++)
            for (int cc = 0; cc < 4; cc++) {
                float acc = 0.0f;
                for (int k = 0; k < 4; k++)
                    acc += P[r][k] * Bd[k * 4 + cc];
                g_F[b][r * 4 + cc] = acc;
            }
    }
    int b = blockIdx.z;
    int ct = blockIdx.y * 32;
    int pt = blockIdx.x * 32;
    int tx = threadIdx.x, ty = threadIdx.y;   // (32,8)
    const float* src = feat + (size_t)b * CQ * PIX;
    #pragma unroll
    for (int j = 0; j < 32; j += 8) {
        int c = ct + ty + j;
        int p = pt + tx;
        if (c < CQ && p < PIX)
            tile[ty + j][tx] = src[(size_t)c * PIX + p];
    }
    __syncthreads();
    __half* dst = (__half*)g_featTh;
    dst += (size_t)b * PIX * (FROW * 8);
    #pragma unroll
    for (int j = 0; j < 32; j += 8) {
        int p = pt + ty + j;
        int c = ct + tx;
        if (c < CQ && p < PIX)
            dst[(size_t)p * (FROW * 8) + c] = __float2half(tile[tx][ty + j]);
    }
}

// ---------------- main kernel ----------------
__global__ void __launch_bounds__(THREADS)
bev_kernel(float* __restrict__ out) {
    __shared__ uint4  s_wh[PTS_PER_BLK];                // 4 broadcast half2 weights
    __shared__ int4   s_idx4[PTS_PER_BLK];              // pixel * FROW (uint4 base)
    __shared__ uint4  s_stg[PTS_PER_BLK * (SROWU / 4)]; // 64 rows x 16 uint4 (fp16, swizzled)

    const int bidx = blockIdx.x;
    const int b = bidx >> 12;                 // 4096 blocks per batch
    const int nbase = (bidx & 4095) * PTS_PER_BLK;
    const int tid = threadIdx.x;

    // ---- Phase A: geometry for 64 points ----
    if (tid < PTS_PER_BLK) {
        int n = nbase + tid;
        int ix = n >> 11;            // NY*NZ = 2048
        int iy = (n >> 4) & 127;     // NZ = 16
        int iz = n & 15;
        float X = -51.2f + ix * 0.8f;
        float Y = -51.2f + iy * 0.8f;
        float Z = -5.0f + iz * 0.5f;
        const float* F = g_F[b];
        float px = F[0] * X + F[1] * Y + F[2]  * Z + F[3];
        float py = F[4] * X + F[5] * Y + F[6]  * Z + F[7];
        float pz = F[8] * X + F[9] * Y + F[10] * Z + F[11];
        float u = px / pz;
        float v = py / pz;
        u = u / (float)WQ * 2.0f - 1.0f;
        v = v / (float)HQ * 2.0f - 1.0f;
        float x = (u + 1.0f) * 0.5f * (float)(WQ - 1);
        float y = (v + 1.0f) * 0.5f * (float)(HQ - 1);
        if (!(isfinite(x) && isfinite(y))) { x = -10.0f; y = -10.0f; }
        float x0f = floorf(x), y0f = floorf(y);
        float wx1 = x - x0f, wy1 = y - y0f;
        float wx0 = 1.0f - wx1, wy0 = 1.0f - wy1;
        float x1f = x0f + 1.0f, y1f = y0f + 1.0f;
        bool vx0 = (x0f >= 0.0f) && (x0f <= (float)(WQ - 1));
        bool vx1 = (x1f >= 0.0f) && (x1f <= (float)(WQ - 1));
        bool vy0 = (y0f >= 0.0f) && (y0f <= (float)(HQ - 1));
        bool vy1 = (y1f >= 0.0f) && (y1f <= (float)(HQ - 1));
        int xi0 = (int)fminf(fmaxf(x0f, 0.0f), (float)(WQ - 1));
        int xi1 = (int)fminf(fmaxf(x1f, 0.0f), (float)(WQ - 1));
        int yi0 = (int)fminf(fmaxf(y0f, 0.0f), (float)(HQ - 1));
        int yi1 = (int)fminf(fmaxf(y1f, 0.0f), (float)(HQ - 1));
        int4 id;
        id.x = (yi0 * WQ + xi0) * FROW;
        id.y = (yi0 * WQ + xi1) * FROW;
        id.z = (yi1 * WQ + xi0) * FROW;
        id.w = (yi1 * WQ + xi1) * FROW;
        s_idx4[tid] = id;
        float w0 = (vx0 && vy0) ? wx0 * wy0 : 0.0f;
        float w1 = (vx1 && vy0) ? wx1 * wy0 : 0.0f;
        float w2 = (vx0 && vy1) ? wx0 * wy1 : 0.0f;
        float w3 = (vx1 && vy1) ? wx1 * wy1 : 0.0f;
        __half2 h0 = __float2half2_rn(w0);
        __half2 h1 = __float2half2_rn(w1);
        __half2 h2 = __float2half2_rn(w2);
        __half2 h3 = __float2half2_rn(w3);
        uint4 wh;
        wh.x = *reinterpret_cast<unsigned*>(&h0);
        wh.y = *reinterpret_cast<unsigned*>(&h1);
        wh.z = *reinterpret_cast<unsigned*>(&h2);
        wh.w = *reinterpret_cast<unsigned*>(&h3);
        s_wh[tid] = wh;
    }
    __syncthreads();

    // ---- Phase B: predicated fp16 LDG.128 gathers (8 ch) + HFMA2 combine -> fp16 staging ----
    const uint4* fT = g_featTh + (size_t)b * PIX * FROW;
    #pragma unroll
    for (int it = 0; it < 2; it++) {
        int i = it * THREADS + tid;   // 0..639
        int p = i / NG8;
        int g = i - p * NG8;
        uint4 wh = s_wh[p];
        int4 id = s_idx4[p];
        __half2 acc0 = __float2half2_rn(0.f);
        __half2 acc1 = acc0, acc2 = acc0, acc3 = acc0;
        #define CORNER(WU, IDK)                                              \
            if (WU != 0u) {                                                  \
                uint4 raw = __ldg(&fT[IDK + g]);                             \
                __half2 wk = *reinterpret_cast<__half2*>(&WU);               \
                acc0 = __hfma2(wk, *reinterpret_cast<__half2*>(&raw.x), acc0); \
                acc1 = __hfma2(wk, *reinterpret_cast<__half2*>(&raw.y), acc1); \
                acc2 = __hfma2(wk, *reinterpret_cast<__half2*>(&raw.z), acc2); \
                acc3 = __hfma2(wk, *reinterpret_cast<__half2*>(&raw.w), acc3); \
            }
        CORNER(wh.x, id.x)
        CORNER(wh.y, id.y)
        CORNER(wh.z, id.z)
        CORNER(wh.w, id.w)
        #undef CORNER
        uint4 st;
        st.x = *reinterpret_cast<unsigned*>(&acc0);
        st.y = *reinterpret_cast<unsigned*>(&acc1);
        st.z = *reinterpret_cast<unsigned*>(&acc2);
        st.w = *reinterpret_cast<unsigned*>(&acc3);
        int p4 = p >> 2;
        int G = p4 & 7;
        if ((p4 & 8) != 0) st = make_uint4(st.z, st.w, st.x, st.y);
        s_stg[p * (SROWU / 4) + (g ^ G)] = st;
    }
    __syncthreads();

    // ---- Phase C: conflict-free LDS.32 (half2 = channel pair) + 2x coalesced STG.128 ----
    {
        const unsigned* s_u = (const unsigned*)s_stg;
        float4* out4 = (float4*)out;
        #pragma unroll
        for (int it = 0; it < 2; it++) {
            int i = it * THREADS + tid;   // 0..639
            int cp = i >> 4;              // channel-pair 0..39
            int p4 = i & 15;              // point-quad 0..15
            int G = p4 & 7;
            int rx = p4 >> 3;
            int word = 4 * ((cp >> 2) ^ G) + ((cp + 2 * rx) & 3);
            int base = (4 * p4) * SROWU + word;
            unsigned u0 = s_u[base + 0 * SROWU];
            unsigned u1 = s_u[base + 1 * SROWU];
            unsigned u2 = s_u[base + 2 * SROWU];
            unsigned u3 = s_u[base + 3 * SROWU];
            float2 f0 = __half22float2(*reinterpret_cast<__half2*>(&u0));
            float2 f1 = __half22float2(*reinterpret_cast<__half2*>(&u1));
            float2 f2 = __half22float2(*reinterpret_cast<__half2*>(&u2));
            float2 f3 = __half22float2(*reinterpret_cast<__half2*>(&u3));
            int c0 = 2 * cp;
            size_t idx0 = (size_t)(b * CQ + c0) * (NPTS / 4) + (nbase >> 2) + p4;
            size_t idx1 = idx0 + (NPTS / 4);
            out4[idx0] = make_float4(f0.x, f1.x, f2.x, f3.x);
            out4[idx1] = make_float4(f0.y, f1.y, f2.y, f3.y);
        }
    }
}

extern "C" void kernel_launch(void* const* d_in, const int* in_sizes, int n_in,
                              void* d_out, int out_size) {
    const float* img_feats = (const float*)d_in[0];
    const float* intrin    = (const float*)d_in[1];
    const float* extrin    = (const float*)d_in[2];
    const float* bda       = (const float*)d_in[3];
    float* out = (float*)d_out;

    dim3 tgrid((PIX + 31) / 32, (CQ + 31) / 32, BQ);
    prep_kernel<<<tgrid, dim3(32, 8)>>>(img_feats, intrin, extrin, bda);

    int nblocks = BQ * (NPTS / PTS_PER_BLK);   // 8192
    bev_kernel<<<nblocks, THREADS>>>(out);
}

// round 9
// speedup vs baseline: 2.0968x; 1.0484x over previous
#include <cuda_runtime.h>
#include <cuda_fp16.h>
#include <math.h>

#define BQ 2
#define CQ 80
#define HQ 32
#define WQ 88
#define PIX (HQ * WQ)          // 2816 pixels
#define NPTS 262144            // 128*128*16 points per batch
#define PTS_PER_BLK 128
#define THREADS 320
#define NG8 10                 // 80 channels = 10 groups of 8 (uint4 of halves)
#define FROW 12                // feature row stride in uint4 (192B, padded from 160B)
#define ITEMS8 (PTS_PER_BLK * NG8)      // 1280 gather items per block
#define ITEMSC (PTS_PER_BLK / 4 * 40)   // 1280 store items (channel-pair x point-quad)
#define SROWU 64               // staging row stride in uints (16 uint4 = 256B, 0 mod 32 banks)

// Transposed features in fp16: (B, H*W, Cpad), 8 channels per uint4, 12 uint4/pixel.
__device__ uint4 g_featTh[BQ * PIX * FROW];
// Combined 3x4 projection matrix per batch: F = (intr*scale) * extr * bda
__device__ float g_F[BQ][12];

// ---------------- prep: tiled transpose (B,C,HW) -> (B,HW,Cpad) fp16 + matrices ----------------
__global__ void prep_kernel(const float* __restrict__ feat,
                            const float* __restrict__ intrin,
                            const float* __restrict__ extrin,
                            const float* __restrict__ bda) {
    __shared__ float tile[32][33];
    if (blockIdx.x == 0 && blockIdx.y == 0 && blockIdx.z == 0 &&
        threadIdx.y == 0 && threadIdx.x < BQ) {
        int b = threadIdx.x;
        const float* In = intrin + b * 16;
        const float* Ex = extrin + b * 16;
        const float* Bd = bda + b * 16;
        float P[3][4];
        for (int r = 0; r < 3; r++) {
            float s = (r < 2) ? 0.125f : 1.0f;
            for (int cc = 0; cc < 4; cc++) {
                float acc = 0.0f;
                for (int k = 0; k < 3; k++)
                    acc += In[r * 4 + k] * s * Ex[k * 4 + cc];
                P[r][cc] = acc;
            }
        }
        for (int r = 0; r < 3; r++)
            for (int cc = 0; cc < 4; cc++) {
                float acc = 0.0f;
                for (int k = 0; k < 4; k++)
                    acc += P[r][k] * Bd[k * 4 + cc];
                g_F[b][r * 4 + cc] = acc;
            }
    }
    int b = blockIdx.z;
    int ct = blockIdx.y * 32;
    int pt = blockIdx.x * 32;
    int tx = threadIdx.x, ty = threadIdx.y;   // (32,8)
    const float* src = feat + (size_t)b * CQ * PIX;
    #pragma unroll
    for (int j = 0; j < 32; j += 8) {
        int c = ct + ty + j;
        int p = pt + tx;
        if (c < CQ && p < PIX)
            tile[ty + j][tx] = src[(size_t)c * PIX + p];
    }
    __syncthreads();
    __half* dst = (__half*)g_featTh;
    dst += (size_t)b * PIX * (FROW * 8);
    #pragma unroll
    for (int j = 0; j < 32; j += 8) {
        int p = pt + ty + j;
        int c = ct + tx;
        if (c < CQ && p < PIX)
            dst[(size_t)p * (FROW * 8) + c] = __float2half(tile[tx][ty + j]);
    }
}

// ---------------- main kernel ----------------
__global__ void __launch_bounds__(THREADS)
bev_kernel(float* __restrict__ out) {
    __shared__ uint4  s_wh[PTS_PER_BLK];                // 4 broadcast half2 weights
    __shared__ int4   s_idx4[PTS_PER_BLK];              // pixel * FROW (uint4 base)
    __shared__ uint4  s_stg[PTS_PER_BLK * (SROWU / 4)]; // 128 rows x 16 uint4 (fp16, swizzled)

    const int bidx = blockIdx.x;
    const int b = bidx >> 11;                 // 2048 blocks per batch
    const int nbase = (bidx & 2047) * PTS_PER_BLK;
    const int tid = threadIdx.x;

    // ---- Phase A: geometry for 128 points ----
    if (tid < PTS_PER_BLK) {
        int n = nbase + tid;
        int ix = n >> 11;            // NY*NZ = 2048
        int iy = (n >> 4) & 127;     // NZ = 16
        int iz = n & 15;
        float X = -51.2f + ix * 0.8f;
        float Y = -51.2f + iy * 0.8f;
        float Z = -5.0f + iz * 0.5f;
        const float* F = g_F[b];
        float px = F[0] * X + F[1] * Y + F[2]  * Z + F[3];
        float py = F[4] * X + F[5] * Y + F[6]  * Z + F[7];
        float pz = F[8] * X + F[9] * Y + F[10] * Z + F[11];
        float u = px / pz;
        float v = py / pz;
        u = u / (float)WQ * 2.0f - 1.0f;
        v = v / (float)HQ * 2.0f - 1.0f;
        float x = (u + 1.0f) * 0.5f * (float)(WQ - 1);
        float y = (v + 1.0f) * 0.5f * (float)(HQ - 1);
        if (!(isfinite(x) && isfinite(y))) { x = -10.0f; y = -10.0f; }
        float x0f = floorf(x), y0f = floorf(y);
        float wx1 = x - x0f, wy1 = y - y0f;
        float wx0 = 1.0f - wx1, wy0 = 1.0f - wy1;
        float x1f = x0f + 1.0f, y1f = y0f + 1.0f;
        bool vx0 = (x0f >= 0.0f) && (x0f <= (float)(WQ - 1));
        bool vx1 = (x1f >= 0.0f) && (x1f <= (float)(WQ - 1));
        bool vy0 = (y0f >= 0.0f) && (y0f <= (float)(HQ - 1));
        bool vy1 = (y1f >= 0.0f) && (y1f <= (float)(HQ - 1));
        int xi0 = (int)fminf(fmaxf(x0f, 0.0f), (float)(WQ - 1));
        int xi1 = (int)fminf(fmaxf(x1f, 0.0f), (float)(WQ - 1));
        int yi0 = (int)fminf(fmaxf(y0f, 0.0f), (float)(HQ - 1));
        int yi1 = (int)fminf(fmaxf(y1f, 0.0f), (float)(HQ - 1));
        int4 id;
        id.x = (yi0 * WQ + xi0) * FROW;
        id.y = (yi0 * WQ + xi1) * FROW;
        id.z = (yi1 * WQ + xi0) * FROW;
        id.w = (yi1 * WQ + xi1) * FROW;
        s_idx4[tid] = id;
        float w0 = (vx0 && vy0) ? wx0 * wy0 : 0.0f;
        float w1 = (vx1 && vy0) ? wx1 * wy0 : 0.0f;
        float w2 = (vx0 && vy1) ? wx0 * wy1 : 0.0f;
        float w3 = (vx1 && vy1) ? wx1 * wy1 : 0.0f;
        __half2 h0 = __float2half2_rn(w0);
        __half2 h1 = __float2half2_rn(w1);
        __half2 h2 = __float2half2_rn(w2);
        __half2 h3 = __float2half2_rn(w3);
        uint4 wh;
        wh.x = *reinterpret_cast<unsigned*>(&h0);
        wh.y = *reinterpret_cast<unsigned*>(&h1);
        wh.z = *reinterpret_cast<unsigned*>(&h2);
        wh.w = *reinterpret_cast<unsigned*>(&h3);
        s_wh[tid] = wh;
    }
    __syncthreads();

    // ---- Phase B: predicated fp16 LDG.128 gathers (8 ch) + HFMA2 combine -> fp16 staging ----
    // Store word-rotated by rx = p4>>3 (0..3) so Phase C is conflict-free.
    const uint4* fT = g_featTh + (size_t)b * PIX * FROW;
    #pragma unroll
    for (int it = 0; it < 4; it++) {
        int i = it * THREADS + tid;   // 0..1279
        int p = i / NG8;
        int g = i - p * NG8;
        uint4 wh = s_wh[p];
        int4 id = s_idx4[p];
        __half2 acc0 = __float2half2_rn(0.f);
        __half2 acc1 = acc0, acc2 = acc0, acc3 = acc0;
        #define CORNER(WU, IDK)                                              \
            if (WU != 0u) {                                                  \
                uint4 raw = __ldg(&fT[IDK + g]);                             \
                __half2 wk = *reinterpret_cast<__half2*>(&WU);               \
                acc0 = __hfma2(wk, *reinterpret_cast<__half2*>(&raw.x), acc0); \
                acc1 = __hfma2(wk, *reinterpret_cast<__half2*>(&raw.y), acc1); \
                acc2 = __hfma2(wk, *reinterpret_cast<__half2*>(&raw.z), acc2); \
                acc3 = __hfma2(wk, *reinterpret_cast<__half2*>(&raw.w), acc3); \
            }
        CORNER(wh.x, id.x)
        CORNER(wh.y, id.y)
        CORNER(wh.z, id.z)
        CORNER(wh.w, id.w)
        #undef CORNER
        uint4 st;
        st.x = *reinterpret_cast<unsigned*>(&acc0);
        st.y = *reinterpret_cast<unsigned*>(&acc1);
        st.z = *reinterpret_cast<unsigned*>(&acc2);
        st.w = *reinterpret_cast<unsigned*>(&acc3);
        int p4 = p >> 2;
        int G = p4 & 7;
        int rx = p4 >> 3;             // 0..3: rotate words right by rx
        uint4 r = st;
        if (rx == 1) r = make_uint4(st.w, st.x, st.y, st.z);
        else if (rx == 2) r = make_uint4(st.z, st.w, st.x, st.y);
        else if (rx == 3) r = make_uint4(st.y, st.z, st.w, st.x);
        s_stg[p * (SROWU / 4) + (g ^ G)] = r;
    }
    __syncthreads();

    // ---- Phase C: conflict-free LDS.32 (half2 = channel pair) + 2x coalesced STG.128 ----
    {
        const unsigned* s_u = (const unsigned*)s_stg;
        float4* out4 = (float4*)out;
        #pragma unroll
        for (int it = 0; it < 4; it++) {
            int i = it * THREADS + tid;   // 0..1279
            int cp = i >> 5;              // channel-pair 0..39
            int p4 = i & 31;              // point-quad 0..31
            int G = p4 & 7;
            int rx = p4 >> 3;             // 0..3
            int word = 4 * ((cp >> 2) ^ G) + ((cp + rx) & 3);
            int base = (4 * p4) * SROWU + word;
            unsigned u0 = s_u[base + 0 * SROWU];
            unsigned u1 = s_u[base + 1 * SROWU];
            unsigned u2 = s_u[base + 2 * SROWU];
            unsigned u3 = s_u[base + 3 * SROWU];
            float2 f0 = __half22float2(*reinterpret_cast<__half2*>(&u0));
            float2 f1 = __half22float2(*reinterpret_cast<__half2*>(&u1));
            float2 f2 = __half22float2(*reinterpret_cast<__half2*>(&u2));
            float2 f3 = __half22float2(*reinterpret_cast<__half2*>(&u3));
            int c0 = 2 * cp;
            size_t idx0 = (size_t)(b * CQ + c0) * (NPTS / 4) + (nbase >> 2) + p4;
            size_t idx1 = idx0 + (NPTS / 4);
            out4[idx0] = make_float4(f0.x, f1.x, f2.x, f3.x);
            out4[idx1] = make_float4(f0.y, f1.y, f2.y, f3.y);
        }
    }
}

extern "C" void kernel_launch(void* const* d_in, const int* in_sizes, int n_in,
                              void* d_out, int out_size) {
    const float* img_feats = (const float*)d_in[0];
    const float* intrin    = (const float*)d_in[1];
    const float* extrin    = (const float*)d_in[2];
    const float* bda       = (const float*)d_in[3];
    float* out = (float*)d_out;

    dim3 tgrid((PIX + 31) / 32, (CQ + 31) / 32, BQ);
    prep_kernel<<<tgrid, dim3(32, 8)>>>(img_feats, intrin, extrin, bda);

    int nblocks = BQ * (NPTS / PTS_PER_BLK);   // 4096
    bev_kernel<<<nblocks, THREADS>>>(out);
}